// round 11
// baseline (speedup 1.0000x reference)
#include <cuda_runtime.h>
#include <cuda_fp16.h>
#include <cstdint>

// ---------------- problem constants ----------------
#define L_ 8
#define D_ 24
#define THREADS 256              // 6 consumer warps + 2 producer warps

// ---------------- smem layout (per buffer) ----------------
#define XROW_B 80                 // 32 ci fp16 (64B) + 16B pad (bank-safe, 16B aligned)
#define XS_SZ  30160              // 377 rows x 80 B
#define BS_SZ  27648              // 18 ks x 32 lane x 48 B (words 8-11 of each group unused)
#define BUFSTRIDE (XS_SZ + BS_SZ) // 57808
#define MB_OFF (2*BUFSTRIDE)      // mbarriers: full0,full1,empty0,empty1 (8B each)
#define SMEM_BYTES (MB_OFF + 64)  // 115680; 2 CTAs: 2*(115680+1024)=233408 <= 233472

__device__ __forceinline__ void mma_f16(float* d, const uint32_t* a, uint32_t b0, uint32_t b1) {
    asm volatile(
        "mma.sync.aligned.m16n8k16.row.col.f32.f16.f16.f32 "
        "{%0,%1,%2,%3}, {%4,%5,%6,%7}, {%8,%9}, {%0,%1,%2,%3};"
        : "+f"(d[0]), "+f"(d[1]), "+f"(d[2]), "+f"(d[3])
        : "r"(a[0]), "r"(a[1]), "r"(a[2]), "r"(a[3]), "r"(b0), "r"(b1));
}
__device__ __forceinline__ void ldsm_x4(uint32_t* a, uint32_t addr) {
    asm volatile("ldmatrix.sync.aligned.m8n8.x4.shared.b16 {%0,%1,%2,%3}, [%4];"
                 : "=r"(a[0]), "=r"(a[1]), "=r"(a[2]), "=r"(a[3]) : "r"(addr));
}
__device__ __forceinline__ uint32_t smem_u32(const void* p) {
    uint32_t a;
    asm("{ .reg .u64 t; cvta.to.shared.u64 t, %1; cvt.u32.u64 %0, t; }" : "=r"(a) : "l"(p));
    return a;
}
__device__ __forceinline__ void cpa16(uint32_t dst, const void* src) {
    asm volatile("cp.async.cg.shared.global [%0], [%1], 16;" :: "r"(dst), "l"(src) : "memory");
}
__device__ __forceinline__ void mbar_wait(uint32_t mbar, uint32_t par) {
    asm volatile(
        "{\n\t.reg .pred P;\n\tWL%=:\n\t"
        "mbarrier.try_wait.parity.shared.b64 P, [%0], %1;\n\t"
        "@P bra.uni WD%=;\n\tbra.uni WL%=;\n\tWD%=:\n\t}"
        :: "r"(mbar), "r"(par) : "memory");
}
__device__ __forceinline__ void mbar_arrive(uint32_t mbar) {
    asm volatile("{\n\t.reg .b64 t;\n\tmbarrier.arrive.shared.b64 t, [%0];\n\t}"
                 :: "r"(mbar) : "memory");
}

// ---------------- device globals ----------------
__device__ __half g_xh[4*8*24*24*24*32];         // x as [n][l][d][h][w][ci] fp16
__device__ uint32_t g_w2[9*4608];                // [slab][ks 18][lane 32][8 words]

__global__ void prep_w(const float* __restrict__ w) {
    int o = blockIdx.x * 256 + threadIdx.x;
    if (o >= 9*4608) return;
    int slab = o / 4608;
    int rem  = o % 4608;
    int ks   = rem / 256;
    int lane = (rem % 256) / 8;
    int wd   = rem % 8;
    int nt = wd >> 1, pair = wd & 1;
    int tig = lane & 3, gr = lane >> 2;
    int t = ks >> 1, kc2 = ks & 1;
    int ci = kc2 * 16 + tig * 2 + pair * 8;
    int co = nt * 8 + gr;
    int kh = t / 3, kw = t % 3;
    int kl = slab / 3, kd = slab % 3;
    float w0 = w[(ci * 32 + co) * 81 + kl * 27 + kd * 9 + kh * 3 + kw];
    float w1 = w[((ci + 1) * 32 + co) * 81 + kl * 27 + kd * 9 + kh * 3 + kw];
    __half2 hv = __floats2half2_rn(w0, w1);
    g_w2[o] = *(uint32_t*)&hv;
}

__global__ void __launch_bounds__(576, 2)
prep_x(const float* __restrict__ x) {
    __shared__ uint32_t sx[576*16];
    int plane = blockIdx.x;                  // (n*8+l)*24+d
    int t = threadIdx.x;                     // hw
    int n = plane / 192, l = (plane / 24) % 8, d = plane % 24;
    const float* base = x + (((size_t)(n*32)*8 + l)*24 + d)*576 + t;
#pragma unroll
    for (int ci2 = 0; ci2 < 16; ci2++) {
        float v0 = base[(size_t)(2*ci2)   * 110592];
        float v1 = base[(size_t)(2*ci2+1) * 110592];
        __half2 hv = __floats2half2_rn(v0, v1);
        sx[t*16 + ci2] = *(uint32_t*)&hv;
    }
    __syncthreads();
    uint32_t* gw = (uint32_t*)g_xh + (size_t)plane * 9216;
#pragma unroll
    for (int k = 0; k < 16; k++) gw[k*576 + t] = sx[k*576 + t];
}

__global__ void __launch_bounds__(THREADS, 2)
conv_mma(const float* __restrict__ bias, float* __restrict__ out)
{
    extern __shared__ char smem[];
    const uint32_t sb = smem_u32(smem);

    const int tid  = threadIdx.x;
    const int wid  = tid >> 5;
    const int lane = tid & 31;
    const int gr   = lane >> 2;
    const int tig  = lane & 3;

    const int od = blockIdx.x, ol = blockIdx.y;
    const int n  = blockIdx.z >> 1;
    const int h  = blockIdx.z & 1;        // 12-row output half
    const int hlo = (h == 0) ? 1 : 0;
    const int l0 = ol > 0 ? ol - 1 : 0;
    const int l1 = ol < L_ - 1 ? ol + 1 : L_ - 1;
    const int d0 = od > 0 ? od - 1 : 0;
    const int d1 = od < D_ - 1 ? od + 1 : D_ - 1;
    const int nd = d1 - d0 + 1;
    const int ns = (l1 - l0 + 1) * nd;

    const uint32_t mb_full0  = sb + MB_OFF;
    const uint32_t mb_full1  = sb + MB_OFF + 8;
    const uint32_t mb_empty0 = sb + MB_OFF + 16;
    const uint32_t mb_empty1 = sb + MB_OFF + 24;

    if (tid == 0) {
        asm volatile("mbarrier.init.shared.b64 [%0], 64;" :: "r"(mb_full0) : "memory");
        asm volatile("mbarrier.init.shared.b64 [%0], 64;" :: "r"(mb_full1) : "memory");
        asm volatile("mbarrier.init.shared.b64 [%0], 6;"  :: "r"(mb_empty0) : "memory");
        asm volatile("mbarrier.init.shared.b64 [%0], 6;"  :: "r"(mb_empty1) : "memory");
    }

    // zero XS halo regions of both buffers (producer writes only interior rows)
    for (int i = tid; i < (2*XS_SZ)/4; i += THREADS) {
        int b = (i < XS_SZ/4) ? 0 : 1;
        int w = (b == 0) ? i : i - XS_SZ/4;
        *(uint32_t*)(smem + b*BUFSTRIDE + w*4) = 0u;
    }
    __syncthreads();   // mbarriers + zero-fill visible; last block-wide sync

    if (wid >= 6) {
        // ================= producer warps (wid 6: x, wid 7: B) =================
        int eph0 = 0, eph1 = 0;
        for (int s = 0; s < ns; s++) {
            const int buf = s & 1;
            if (s >= 2) {
                if (buf == 0) { mbar_wait(mb_empty0, eph0); eph0 ^= 1; }
                else          { mbar_wait(mb_empty1, eph1); eph1 ^= 1; }
            }
            const int lp = l0 + s / nd;
            const int dp = d0 + s % nd;
            if (wid == 6) {
                const __half* xsrc = g_xh + (size_t)(((n*8 + lp)*24 + dp)) * 576 * 32;
                const uint32_t xb = sb + buf * BUFSTRIDE;
                for (int idx = lane; idx < 1248; idx += 32) {
                    int ch = idx & 3;
                    int r  = idx >> 2;              // 0..311
                    int iw = r % 24;
                    int hh_l = r / 24 + hlo;        // 13 valid rows
                    int ih = h * 12 - 1 + hh_l;
                    cpa16(xb + (hh_l * 27 + iw + 1) * XROW_B + ch * 16,
                          xsrc + (ih * 24 + iw) * 32 + ch * 8);
                }
            } else {
                const int kl = ol + 1 - lp, kd = od + 1 - dp;
                const char* bsrc = (const char*)(g_w2 + (kl * 3 + kd) * 4608);
                const uint32_t bb = sb + buf * BUFSTRIDE + XS_SZ;
                for (int i = lane; i < 1152; i += 32) {
                    int grp = i >> 1, half = i & 1;     // (ks*32+lane'), 16B half
                    cpa16(bb + grp * 48 + half * 16,
                          bsrc + grp * 32 + half * 16);
                }
            }
            // ONE counted arrival per lane after its cp.asyncs complete (.noinc)
            asm volatile("cp.async.mbarrier.arrive.noinc.shared.b64 [%0];"
                         :: "r"(buf == 0 ? mb_full0 : mb_full1) : "memory");
        }
        return;
    }

    // ================= consumer warps (wid 0..5), 3 M-tiles each =================
    int mb[3];
    uint32_t qa[3];
#pragma unroll
    for (int j = 0; j < 3; j++) {
        mb[j] = (wid * 3 + j) * 16;
        int r = mb[j] + (lane & 7) + ((lane >> 3) & 1) * 8;
        int q = (r / 24) * 27 + (r % 24);
        qa[j] = sb + q * XROW_B + ((lane >> 4) & 1) * 16;
    }
    const int dtap[9] = {56, 55, 54, 29, 28, 27, 2, 1, 0};   // (2-kh)*27+(2-kw)

    float d[48];   // [j 3][nt 4][4]
#pragma unroll
    for (int i = 0; i < 48; i++) d[i] = 0.f;

    int fph0 = 0, fph1 = 0;
    for (int s = 0; s < ns; s++) {
        const int buf = s & 1;
        if (buf == 0) { mbar_wait(mb_full0, fph0); fph0 ^= 1; }
        else          { mbar_wait(mb_full1, fph1); fph1 ^= 1; }

        const uint32_t bufoff = buf * BUFSTRIDE;
        const uint32_t qa0 = qa[0] + bufoff, qa1 = qa[1] + bufoff, qa2 = qa[2] + bufoff;
        const char* bsl = smem + bufoff + XS_SZ;

#pragma unroll 3
        for (int t = 0; t < 9; t++) {
            const int dt80 = dtap[t] * XROW_B;
#pragma unroll
            for (int kc2 = 0; kc2 < 2; kc2++) {
                uint32_t a0[4], a1[4], a2[4];
                ldsm_x4(a0, qa0 + dt80 + kc2 * 32);
                ldsm_x4(a1, qa1 + dt80 + kc2 * 32);
                ldsm_x4(a2, qa2 + dt80 + kc2 * 32);
                const uint4* bq = (const uint4*)(bsl + ((t * 2 + kc2) * 32 + lane) * 48);
                uint4 v0 = bq[0], v1 = bq[1];
                mma_f16(d + 0,  a0, v0.x, v0.y);
                mma_f16(d + 16, a1, v0.x, v0.y);
                mma_f16(d + 32, a2, v0.x, v0.y);
                mma_f16(d + 4,  a0, v0.z, v0.w);
                mma_f16(d + 20, a1, v0.z, v0.w);
                mma_f16(d + 36, a2, v0.z, v0.w);
                mma_f16(d + 8,  a0, v1.x, v1.y);
                mma_f16(d + 24, a1, v1.x, v1.y);
                mma_f16(d + 40, a2, v1.x, v1.y);
                mma_f16(d + 12, a0, v1.z, v1.w);
                mma_f16(d + 28, a1, v1.z, v1.w);
                mma_f16(d + 44, a2, v1.z, v1.w);
            }
        }
        if (lane == 0) mbar_arrive(buf == 0 ? mb_empty0 : mb_empty1);
    }

    // ---- epilogue: bias + store ----
    const size_t ob = (((size_t)(n * 32) * 8 + ol) * 24 + od) * 576 + h * 288;
#pragma unroll
    for (int j = 0; j < 3; j++) {
        const int m0 = mb[j] + gr, m1 = m0 + 8;
#pragma unroll
        for (int nt = 0; nt < 4; nt++) {
            const int co0 = nt * 8 + tig * 2;
            const float b0 = __ldg(bias + co0);
            const float b1 = __ldg(bias + co0 + 1);
            const float* dd = d + j * 16 + nt * 4;
            float* o0 = out + ob + (size_t)co0 * 110592;
            float* o1 = o0 + 110592;
            o0[m0] = dd[0] + b0;
            o1[m0] = dd[1] + b1;
            o0[m1] = dd[2] + b0;
            o1[m1] = dd[3] + b1;
        }
    }
}

extern "C" void kernel_launch(void* const* d_in, const int* in_sizes, int n_in,
                              void* d_out, int out_size) {
    const float* x    = (const float*)d_in[0];
    const float* w    = (const float*)d_in[1];
    const float* bias = (const float*)d_in[2];
    float* out = (float*)d_out;

    cudaFuncSetAttribute(conv_mma,
                         cudaFuncAttributeMaxDynamicSharedMemorySize, SMEM_BYTES);

    prep_w<<<162, 256>>>(w);                 // 162*256 == 41472
    prep_x<<<768, 576>>>(x);                 // one block per (n,l,d) plane

    dim3 grid(24, L_, 8);                    // (od, ol, n*2 + half)
    conv_mma<<<grid, THREADS, SMEM_BYTES>>>(bias, out);
}

// round 12
// speedup vs baseline: 1.0004x; 1.0004x over previous
#include <cuda_runtime.h>
#include <cuda_fp16.h>
#include <cstdint>

// ---------------- problem constants ----------------
#define L_ 8
#define D_ 24
#define THREADS 320              // 6 consumer warps + 4 producer warps

// ---------------- smem layout (per buffer) ----------------
#define XROW_B 80                 // 32 ci fp16 (64B) + 16B pad (bank-safe, 16B aligned)
#define XS_SZ  30160              // 377 rows x 80 B
#define BS_SZ  27648              // 18 ks x 32 lane x 48 B (last 16B of each 48 unused)
#define BUFSTRIDE (XS_SZ + BS_SZ) // 57808
#define MB_OFF (2*BUFSTRIDE)      // mbarriers: full0,full1,empty0,empty1 (8B each)
#define SMEM_BYTES (MB_OFF + 64)  // 115680; 2 CTAs: 2*(115680+1024)=233408 <= 233472

__device__ __forceinline__ void mma_f16(float* d, const uint32_t* a, uint32_t b0, uint32_t b1) {
    asm volatile(
        "mma.sync.aligned.m16n8k16.row.col.f32.f16.f16.f32 "
        "{%0,%1,%2,%3}, {%4,%5,%6,%7}, {%8,%9}, {%0,%1,%2,%3};"
        : "+f"(d[0]), "+f"(d[1]), "+f"(d[2]), "+f"(d[3])
        : "r"(a[0]), "r"(a[1]), "r"(a[2]), "r"(a[3]), "r"(b0), "r"(b1));
}
__device__ __forceinline__ void ldsm_x4(uint32_t* a, uint32_t addr) {
    asm volatile("ldmatrix.sync.aligned.m8n8.x4.shared.b16 {%0,%1,%2,%3}, [%4];"
                 : "=r"(a[0]), "=r"(a[1]), "=r"(a[2]), "=r"(a[3]) : "r"(addr));
}
__device__ __forceinline__ uint32_t smem_u32(const void* p) {
    uint32_t a;
    asm("{ .reg .u64 t; cvta.to.shared.u64 t, %1; cvt.u32.u64 %0, t; }" : "=r"(a) : "l"(p));
    return a;
}
__device__ __forceinline__ void cpa16(uint32_t dst, const void* src) {
    asm volatile("cp.async.cg.shared.global [%0], [%1], 16;" :: "r"(dst), "l"(src) : "memory");
}
__device__ __forceinline__ void mbar_wait(uint32_t mbar, uint32_t par) {
    asm volatile(
        "{\n\t.reg .pred P;\n\tWL%=:\n\t"
        "mbarrier.try_wait.parity.shared.b64 P, [%0], %1;\n\t"
        "@P bra.uni WD%=;\n\tbra.uni WL%=;\n\tWD%=:\n\t}"
        :: "r"(mbar), "r"(par) : "memory");
}
__device__ __forceinline__ void mbar_arrive(uint32_t mbar) {
    asm volatile("{\n\t.reg .b64 t;\n\tmbarrier.arrive.shared.b64 t, [%0];\n\t}"
                 :: "r"(mbar) : "memory");
}

// ---------------- device globals ----------------
__device__ __half g_xh[4*8*24*24*24*32];         // x as [n][l][d][h][w][ci] fp16
__device__ uint32_t g_w2[9*4608];                // [slab][ks 18][lane 32][8 words]

__global__ void prep_w(const float* __restrict__ w) {
    int o = blockIdx.x * 256 + threadIdx.x;
    if (o >= 9*4608) return;
    int slab = o / 4608;
    int rem  = o % 4608;
    int ks   = rem / 256;
    int lane = (rem % 256) / 8;
    int wd   = rem % 8;
    int nt = wd >> 1, pair = wd & 1;
    int tig = lane & 3, gr = lane >> 2;
    int t = ks >> 1, kc2 = ks & 1;
    int ci = kc2 * 16 + tig * 2 + pair * 8;
    int co = nt * 8 + gr;
    int kh = t / 3, kw = t % 3;
    int kl = slab / 3, kd = slab % 3;
    float w0 = w[(ci * 32 + co) * 81 + kl * 27 + kd * 9 + kh * 3 + kw];
    float w1 = w[((ci + 1) * 32 + co) * 81 + kl * 27 + kd * 9 + kh * 3 + kw];
    __half2 hv = __floats2half2_rn(w0, w1);
    g_w2[o] = *(uint32_t*)&hv;
}

__global__ void __launch_bounds__(576, 2)
prep_x(const float* __restrict__ x) {
    __shared__ uint32_t sx[576*16];
    int plane = blockIdx.x;                  // (n*8+l)*24+d
    int t = threadIdx.x;                     // hw
    int n = plane / 192, l = (plane / 24) % 8, d = plane % 24;
    const float* base = x + (((size_t)(n*32)*8 + l)*24 + d)*576 + t;
#pragma unroll
    for (int ci2 = 0; ci2 < 16; ci2++) {
        float v0 = base[(size_t)(2*ci2)   * 110592];
        float v1 = base[(size_t)(2*ci2+1) * 110592];
        __half2 hv = __floats2half2_rn(v0, v1);
        sx[t*16 + ci2] = *(uint32_t*)&hv;
    }
    __syncthreads();
    uint32_t* gw = (uint32_t*)g_xh + (size_t)plane * 9216;
#pragma unroll
    for (int k = 0; k < 16; k++) gw[k*576 + t] = sx[k*576 + t];
}

__global__ void __launch_bounds__(THREADS, 2)
conv_mma(const float* __restrict__ bias, float* __restrict__ out)
{
    extern __shared__ char smem[];
    const uint32_t sb = smem_u32(smem);

    const int tid  = threadIdx.x;
    const int wid  = tid >> 5;
    const int lane = tid & 31;
    const int gr   = lane >> 2;
    const int tig  = lane & 3;

    const int od = blockIdx.x, ol = blockIdx.y;
    const int n  = blockIdx.z >> 1;
    const int h  = blockIdx.z & 1;        // 12-row output half
    const int hlo = (h == 0) ? 1 : 0;
    const int l0 = ol > 0 ? ol - 1 : 0;
    const int l1 = ol < L_ - 1 ? ol + 1 : L_ - 1;
    const int d0 = od > 0 ? od - 1 : 0;
    const int d1 = od < D_ - 1 ? od + 1 : D_ - 1;
    const int nd = d1 - d0 + 1;
    const int ns = (l1 - l0 + 1) * nd;

    const uint32_t mb_full0  = sb + MB_OFF;
    const uint32_t mb_full1  = sb + MB_OFF + 8;
    const uint32_t mb_empty0 = sb + MB_OFF + 16;
    const uint32_t mb_empty1 = sb + MB_OFF + 24;

    if (tid == 0) {
        asm volatile("mbarrier.init.shared.b64 [%0], 128;" :: "r"(mb_full0) : "memory");
        asm volatile("mbarrier.init.shared.b64 [%0], 128;" :: "r"(mb_full1) : "memory");
        asm volatile("mbarrier.init.shared.b64 [%0], 6;"   :: "r"(mb_empty0) : "memory");
        asm volatile("mbarrier.init.shared.b64 [%0], 6;"   :: "r"(mb_empty1) : "memory");
    }

    // zero XS halo regions of both buffers (producers write only interior rows)
    for (int i = tid; i < (2*XS_SZ)/4; i += THREADS) {
        int b = (i < XS_SZ/4) ? 0 : 1;
        int w = (b == 0) ? i : i - XS_SZ/4;
        *(uint32_t*)(smem + b*BUFSTRIDE + w*4) = 0u;
    }
    __syncthreads();   // mbarriers + zero-fill visible; last block-wide sync

    if (wid >= 6) {
        // ============ producer warps (wid 6..9): 128 lanes share staging ============
        const int pl = (wid - 6) * 32 + lane;   // 0..127
        int eph0 = 0, eph1 = 0;
        for (int s = 0; s < ns; s++) {
            const int buf = s & 1;
            if (s >= 2) {
                if (buf == 0) { mbar_wait(mb_empty0, eph0); eph0 ^= 1; }
                else          { mbar_wait(mb_empty1, eph1); eph1 ^= 1; }
            }
            const int lp = l0 + s / nd;
            const int dp = d0 + s % nd;
            const int kl = ol + 1 - lp, kd = od + 1 - dp;
            // x: 1248 16B chunks
            const __half* xsrc = g_xh + (size_t)(((n*8 + lp)*24 + dp)) * 576 * 32;
            const uint32_t xb = sb + buf * BUFSTRIDE;
            for (int idx = pl; idx < 1248; idx += 128) {
                int ch = idx & 3;
                int r  = idx >> 2;              // 0..311
                int iw = r % 24;
                int hh_l = r / 24 + hlo;        // 13 valid rows
                int ih = h * 12 - 1 + hh_l;
                cpa16(xb + (hh_l * 27 + iw + 1) * XROW_B + ch * 16,
                      xsrc + (ih * 24 + iw) * 32 + ch * 8);
            }
            // B: 1152 16B chunks, gmem 32B groups -> smem 48B stride
            const char* bsrc = (const char*)(g_w2 + (kl * 3 + kd) * 4608);
            const uint32_t bb = sb + buf * BUFSTRIDE + XS_SZ;
            for (int i = pl; i < 1152; i += 128) {
                int grp = i >> 1, half = i & 1;
                cpa16(bb + grp * 48 + half * 16, bsrc + grp * 32 + half * 16);
            }
            // ONE counted arrival per lane after its cp.asyncs complete (.noinc)
            asm volatile("cp.async.mbarrier.arrive.noinc.shared.b64 [%0];"
                         :: "r"(buf == 0 ? mb_full0 : mb_full1) : "memory");
        }
        return;
    }

    // ============ consumer warps (wid 0..5), 3 M-tiles each ============
    int mb[3];
    uint32_t qa[3];
#pragma unroll
    for (int j = 0; j < 3; j++) {
        mb[j] = (wid * 3 + j) * 16;
        int r = mb[j] + (lane & 7) + ((lane >> 3) & 1) * 8;
        int q = (r / 24) * 27 + (r % 24);
        qa[j] = sb + q * XROW_B + ((lane >> 4) & 1) * 16;
    }
    const int dtap[9] = {56, 55, 54, 29, 28, 27, 2, 1, 0};   // (2-kh)*27+(2-kw)

    float d[48];   // [j 3][nt 4][4]
#pragma unroll
    for (int i = 0; i < 48; i++) d[i] = 0.f;

    int fph0 = 0, fph1 = 0;
    for (int s = 0; s < ns; s++) {
        const int buf = s & 1;
        if (buf == 0) { mbar_wait(mb_full0, fph0); fph0 ^= 1; }
        else          { mbar_wait(mb_full1, fph1); fph1 ^= 1; }

        const uint32_t bufoff = buf * BUFSTRIDE;
        const uint32_t qa0 = qa[0] + bufoff, qa1 = qa[1] + bufoff, qa2 = qa[2] + bufoff;
        const char* bsl = smem + bufoff + XS_SZ;

#pragma unroll 3
        for (int t = 0; t < 9; t++) {
            const int dt80 = dtap[t] * XROW_B;
#pragma unroll
            for (int kc2 = 0; kc2 < 2; kc2++) {
                uint32_t a0[4], a1[4], a2[4];
                ldsm_x4(a0, qa0 + dt80 + kc2 * 32);
                ldsm_x4(a1, qa1 + dt80 + kc2 * 32);
                ldsm_x4(a2, qa2 + dt80 + kc2 * 32);
                const uint4* bq = (const uint4*)(bsl + ((t * 2 + kc2) * 32 + lane) * 48);
                uint4 v0 = bq[0], v1 = bq[1];
                mma_f16(d + 0,  a0, v0.x, v0.y);
                mma_f16(d + 16, a1, v0.x, v0.y);
                mma_f16(d + 32, a2, v0.x, v0.y);
                mma_f16(d + 4,  a0, v0.z, v0.w);
                mma_f16(d + 20, a1, v0.z, v0.w);
                mma_f16(d + 36, a2, v0.z, v0.w);
                mma_f16(d + 8,  a0, v1.x, v1.y);
                mma_f16(d + 24, a1, v1.x, v1.y);
                mma_f16(d + 40, a2, v1.x, v1.y);
                mma_f16(d + 12, a0, v1.z, v1.w);
                mma_f16(d + 28, a1, v1.z, v1.w);
                mma_f16(d + 44, a2, v1.z, v1.w);
            }
        }
        if (lane == 0) mbar_arrive(buf == 0 ? mb_empty0 : mb_empty1);
    }

    // ---- epilogue: bias + store ----
    const size_t ob = (((size_t)(n * 32) * 8 + ol) * 24 + od) * 576 + h * 288;
#pragma unroll
    for (int j = 0; j < 3; j++) {
        const int m0 = mb[j] + gr, m1 = m0 + 8;
#pragma unroll
        for (int nt = 0; nt < 4; nt++) {
            const int co0 = nt * 8 + tig * 2;
            const float b0 = __ldg(bias + co0);
            const float b1 = __ldg(bias + co0 + 1);
            const float* dd = d + j * 16 + nt * 4;
            float* o0 = out + ob + (size_t)co0 * 110592;
            float* o1 = o0 + 110592;
            o0[m0] = dd[0] + b0;
            o1[m0] = dd[1] + b1;
            o0[m1] = dd[2] + b0;
            o1[m1] = dd[3] + b1;
        }
    }
}

extern "C" void kernel_launch(void* const* d_in, const int* in_sizes, int n_in,
                              void* d_out, int out_size) {
    const float* x    = (const float*)d_in[0];
    const float* w    = (const float*)d_in[1];
    const float* bias = (const float*)d_in[2];
    float* out = (float*)d_out;

    cudaFuncSetAttribute(conv_mma,
                         cudaFuncAttributeMaxDynamicSharedMemorySize, SMEM_BYTES);

    prep_w<<<162, 256>>>(w);                 // 162*256 == 41472
    prep_x<<<768, 576>>>(x);                 // one block per (n,l,d) plane

    dim3 grid(24, L_, 8);                    // (od, ol, n*2 + half)
    conv_mma<<<grid, THREADS, SMEM_BYTES>>>(bias, out);
}

// round 13
// speedup vs baseline: 1.0682x; 1.0677x over previous
#include <cuda_runtime.h>
#include <cuda_fp16.h>
#include <cstdint>

// ---------------- problem constants ----------------
#define L_ 8
#define D_ 24
#define THREADS 320              // 9 consumer warps + 1 producer warp

// ---------------- smem layout (per buffer) ----------------
#define XROW_B 80                 // 32 ci fp16 (64B) + 16B pad (bank-safe, 16B aligned)
#define XS_SZ  30160              // 377 rows x 80 B
#define BS_SZ  27648              // 18 ks x 32 lane x 48 B (last 16B of each 48 unused)
#define BUFSTRIDE (XS_SZ + BS_SZ) // 57808
#define MB_OFF (2*BUFSTRIDE)      // mbarriers: full0,full1,empty0,empty1 (8B each)
#define SMEM_BYTES (MB_OFF + 64)  // 115680; 2 CTAs: 2*(115680+1024)=233408 <= 233472

__device__ __forceinline__ void mma_f16(float* d, const uint32_t* a, uint32_t b0, uint32_t b1) {
    asm volatile(
        "mma.sync.aligned.m16n8k16.row.col.f32.f16.f16.f32 "
        "{%0,%1,%2,%3}, {%4,%5,%6,%7}, {%8,%9}, {%0,%1,%2,%3};"
        : "+f"(d[0]), "+f"(d[1]), "+f"(d[2]), "+f"(d[3])
        : "r"(a[0]), "r"(a[1]), "r"(a[2]), "r"(a[3]), "r"(b0), "r"(b1));
}
__device__ __forceinline__ void ldsm_x4(uint32_t* a, uint32_t addr) {
    asm volatile("ldmatrix.sync.aligned.m8n8.x4.shared.b16 {%0,%1,%2,%3}, [%4];"
                 : "=r"(a[0]), "=r"(a[1]), "=r"(a[2]), "=r"(a[3]) : "r"(addr));
}
__device__ __forceinline__ uint32_t smem_u32(const void* p) {
    uint32_t a;
    asm("{ .reg .u64 t; cvta.to.shared.u64 t, %1; cvt.u32.u64 %0, t; }" : "=r"(a) : "l"(p));
    return a;
}
__device__ __forceinline__ void cpa16(uint32_t dst, const void* src) {
    asm volatile("cp.async.cg.shared.global [%0], [%1], 16;" :: "r"(dst), "l"(src) : "memory");
}
__device__ __forceinline__ void mbar_wait(uint32_t mbar, uint32_t par) {
    asm volatile(
        "{\n\t.reg .pred P;\n\tWL%=:\n\t"
        "mbarrier.try_wait.parity.shared.b64 P, [%0], %1;\n\t"
        "@P bra.uni WD%=;\n\tbra.uni WL%=;\n\tWD%=:\n\t}"
        :: "r"(mbar), "r"(par) : "memory");
}
__device__ __forceinline__ void mbar_arrive(uint32_t mbar) {
    asm volatile("{\n\t.reg .b64 t;\n\tmbarrier.arrive.shared.b64 t, [%0];\n\t}"
                 :: "r"(mbar) : "memory");
}

// ---------------- device globals ----------------
__device__ __half g_xh[4*8*24*24*24*32];         // x as [n][l][d][h][w][ci] fp16
__device__ uint32_t g_w2[9*4608];                // [slab][ks 18][lane 32][8 words]

__global__ void prep_w(const float* __restrict__ w) {
    int o = blockIdx.x * 256 + threadIdx.x;
    if (o >= 9*4608) return;
    int slab = o / 4608;
    int rem  = o % 4608;
    int ks   = rem / 256;
    int lane = (rem % 256) / 8;
    int wd   = rem % 8;
    int nt = wd >> 1, pair = wd & 1;
    int tig = lane & 3, gr = lane >> 2;
    int t = ks >> 1, kc2 = ks & 1;
    int ci = kc2 * 16 + tig * 2 + pair * 8;
    int co = nt * 8 + gr;
    int kh = t / 3, kw = t % 3;
    int kl = slab / 3, kd = slab % 3;
    float w0 = w[(ci * 32 + co) * 81 + kl * 27 + kd * 9 + kh * 3 + kw];
    float w1 = w[((ci + 1) * 32 + co) * 81 + kl * 27 + kd * 9 + kh * 3 + kw];
    __half2 hv = __floats2half2_rn(w0, w1);
    g_w2[o] = *(uint32_t*)&hv;
}

__global__ void __launch_bounds__(576, 2)
prep_x(const float* __restrict__ x) {
    __shared__ uint32_t sx[576*16];
    int plane = blockIdx.x;                  // (n*8+l)*24+d
    int t = threadIdx.x;                     // hw
    int n = plane / 192, l = (plane / 24) % 8, d = plane % 24;
    const float* base = x + (((size_t)(n*32)*8 + l)*24 + d)*576 + t;
#pragma unroll
    for (int ci2 = 0; ci2 < 16; ci2++) {
        float v0 = base[(size_t)(2*ci2)   * 110592];
        float v1 = base[(size_t)(2*ci2+1) * 110592];
        __half2 hv = __floats2half2_rn(v0, v1);
        sx[t*16 + ci2] = *(uint32_t*)&hv;
    }
    __syncthreads();
    uint32_t* gw = (uint32_t*)g_xh + (size_t)plane * 9216;
#pragma unroll
    for (int k = 0; k < 16; k++) gw[k*576 + t] = sx[k*576 + t];
}

__global__ void __launch_bounds__(THREADS, 2)
conv_mma(const float* __restrict__ bias, float* __restrict__ out)
{
    extern __shared__ char smem[];
    const uint32_t sb = smem_u32(smem);

    const int tid  = threadIdx.x;
    const int wid  = tid >> 5;
    const int lane = tid & 31;
    const int gr   = lane >> 2;
    const int tig  = lane & 3;

    const int od = blockIdx.x, ol = blockIdx.y;
    const int n  = blockIdx.z >> 1;
    const int h  = blockIdx.z & 1;        // 12-row output half
    const int hlo = (h == 0) ? 1 : 0;     // first staged hh_l
    const int l0 = ol > 0 ? ol - 1 : 0;
    const int l1 = ol < L_ - 1 ? ol + 1 : L_ - 1;
    const int d0 = od > 0 ? od - 1 : 0;
    const int d1 = od < D_ - 1 ? od + 1 : D_ - 1;
    const int nd = d1 - d0 + 1;
    const int ns = (l1 - l0 + 1) * nd;

    const uint32_t mb_full0  = sb + MB_OFF;
    const uint32_t mb_full1  = sb + MB_OFF + 8;
    const uint32_t mb_empty0 = sb + MB_OFF + 16;
    const uint32_t mb_empty1 = sb + MB_OFF + 24;

    if (tid == 0) {
        asm volatile("mbarrier.init.shared.b64 [%0], 32;" :: "r"(mb_full0) : "memory");
        asm volatile("mbarrier.init.shared.b64 [%0], 32;" :: "r"(mb_full1) : "memory");
        asm volatile("mbarrier.init.shared.b64 [%0], 9;"  :: "r"(mb_empty0) : "memory");
        asm volatile("mbarrier.init.shared.b64 [%0], 9;"  :: "r"(mb_empty1) : "memory");
    }

    // ---- halo-only zero-fill: 66 slots/buffer (1 halo row + 3 side cols x 13 rows) ----
    {
        const int hrow = (h == 0) ? 0 : 13;   // the out-of-range h row
        const uint4 z4 = make_uint4(0u, 0u, 0u, 0u);
        for (int i = tid; i < 2 * 66 * 5; i += THREADS) {
            int buf  = i / 330;
            int r    = i % 330;
            int slot = r / 5;
            int seg  = r % 5;
            int q;
            if (slot < 27) {
                q = hrow * 27 + slot;
            } else {
                int s   = slot - 27;
                int row = hlo + s / 3;
                int c   = s % 3;
                int ww  = (c == 0) ? 0 : 24 + c;   // ww in {0,25,26}
                q = row * 27 + ww;
            }
            if (q < 377)
                *(uint4*)(smem + buf * BUFSTRIDE + q * XROW_B + seg * 16) = z4;
        }
    }
    __syncthreads();   // mbarriers + halo zero visible; last block-wide sync

    if (wid == 9) {
        // ================= producer warp =================
        int eph0 = 0, eph1 = 0;
        for (int s = 0; s < ns; s++) {
            const int buf = s & 1;
            if (s >= 2) {
                if (buf == 0) { mbar_wait(mb_empty0, eph0); eph0 ^= 1; }
                else          { mbar_wait(mb_empty1, eph1); eph1 ^= 1; }
            }
            const int lp = l0 + s / nd;
            const int dp = d0 + s % nd;
            const int kl = ol + 1 - lp, kd = od + 1 - dp;
            // x: 1248 16B chunks (13 valid rows x 24 w x 4 chunks)
            const __half* xsrc = g_xh + (size_t)(((n*8 + lp)*24 + dp)) * 576 * 32;
            const uint32_t xb = sb + buf * BUFSTRIDE;
            for (int idx = lane; idx < 1248; idx += 32) {
                int ch = idx & 3;
                int r  = idx >> 2;              // 0..311
                int iw = r % 24;
                int hh_l = r / 24 + hlo;
                int ih = h * 12 - 1 + hh_l;
                cpa16(xb + (hh_l * 27 + iw + 1) * XROW_B + ch * 16,
                      xsrc + (ih * 24 + iw) * 32 + ch * 8);
            }
            // B: 1152 16B chunks, gmem 32B groups -> smem 48B stride
            const char* bsrc = (const char*)(g_w2 + (kl * 3 + kd) * 4608);
            const uint32_t bb = xb + XS_SZ;
            for (int i = lane; i < 1152; i += 32) {
                int grp = i >> 1, half = i & 1;
                cpa16(bb + grp * 48 + half * 16, bsrc + grp * 32 + half * 16);
            }
            // ONE counted arrival per lane once its cp.asyncs complete (.noinc)
            asm volatile("cp.async.mbarrier.arrive.noinc.shared.b64 [%0];"
                         :: "r"(buf == 0 ? mb_full0 : mb_full1) : "memory");
        }
        return;
    }

    // ================= consumer warps (wid 0..8), 2 M-tiles each =================
    int mb[2];
    uint32_t qa[2];
#pragma unroll
    for (int j = 0; j < 2; j++) {
        mb[j] = (wid * 2 + j) * 16;
        int r = mb[j] + (lane & 7) + ((lane >> 3) & 1) * 8;
        int q = (r / 24) * 27 + (r % 24);
        qa[j] = sb + q * XROW_B + ((lane >> 4) & 1) * 16;
    }
    const int dtap[9] = {56, 55, 54, 29, 28, 27, 2, 1, 0};   // (2-kh)*27+(2-kw)

    float d[32];
#pragma unroll
    for (int i = 0; i < 32; i++) d[i] = 0.f;

    int fph0 = 0, fph1 = 0;
    for (int s = 0; s < ns; s++) {
        const int buf = s & 1;
        if (buf == 0) { mbar_wait(mb_full0, fph0); fph0 ^= 1; }
        else          { mbar_wait(mb_full1, fph1); fph1 ^= 1; }

        const uint32_t bufoff = buf * BUFSTRIDE;
        const uint32_t qa0 = qa[0] + bufoff, qa1 = qa[1] + bufoff;
        const char* bsl = smem + bufoff + XS_SZ;

#pragma unroll 9
        for (int t = 0; t < 9; t++) {
            const int dt80 = dtap[t] * XROW_B;
#pragma unroll
            for (int kc2 = 0; kc2 < 2; kc2++) {
                uint32_t a0[4], a1[4];
                ldsm_x4(a0, qa0 + dt80 + kc2 * 32);
                ldsm_x4(a1, qa1 + dt80 + kc2 * 32);
                const uint4* bq = (const uint4*)(bsl + ((t * 2 + kc2) * 32 + lane) * 48);
                uint4 v0 = bq[0], v1 = bq[1];
                mma_f16(d + 0,  a0, v0.x, v0.y);
                mma_f16(d + 16, a1, v0.x, v0.y);
                mma_f16(d + 4,  a0, v0.z, v0.w);
                mma_f16(d + 20, a1, v0.z, v0.w);
                mma_f16(d + 8,  a0, v1.x, v1.y);
                mma_f16(d + 24, a1, v1.x, v1.y);
                mma_f16(d + 12, a0, v1.z, v1.w);
                mma_f16(d + 28, a1, v1.z, v1.w);
            }
        }
        if (lane == 0) mbar_arrive(buf == 0 ? mb_empty0 : mb_empty1);
    }

    // ---- epilogue: bias + store ----
    const size_t ob = (((size_t)(n * 32) * 8 + ol) * 24 + od) * 576 + h * 288;
#pragma unroll
    for (int j = 0; j < 2; j++) {
        const int m0 = mb[j] + gr, m1 = m0 + 8;
#pragma unroll
        for (int nt = 0; nt < 4; nt++) {
            const int co0 = nt * 8 + tig * 2;
            const float b0 = __ldg(bias + co0);
            const float b1 = __ldg(bias + co0 + 1);
            const float* dd = d + j * 16 + nt * 4;
            float* o0 = out + ob + (size_t)co0 * 110592;
            float* o1 = o0 + 110592;
            o0[m0] = dd[0] + b0;
            o1[m0] = dd[1] + b1;
            o0[m1] = dd[2] + b0;
            o1[m1] = dd[3] + b1;
        }
    }
}

extern "C" void kernel_launch(void* const* d_in, const int* in_sizes, int n_in,
                              void* d_out, int out_size) {
    const float* x    = (const float*)d_in[0];
    const float* w    = (const float*)d_in[1];
    const float* bias = (const float*)d_in[2];
    float* out = (float*)d_out;

    cudaFuncSetAttribute(conv_mma,
                         cudaFuncAttributeMaxDynamicSharedMemorySize, SMEM_BYTES);

    prep_w<<<162, 256>>>(w);                 // 162*256 == 41472
    prep_x<<<768, 576>>>(x);                 // one block per (n,l,d) plane

    dim3 grid(24, L_, 8);                    // (od, ol, n*2 + half)
    conv_mma<<<grid, THREADS, SMEM_BYTES>>>(bias, out);
}

// round 14
// speedup vs baseline: 1.0997x; 1.0294x over previous
#include <cuda_runtime.h>
#include <cuda_fp16.h>
#include <cstdint>

// ---------------- problem constants ----------------
#define L_ 8
#define D_ 24
#define THREADS 512              // 12 consumer warps + 4 producer warps

// ---------------- smem layout ----------------
#define XROW_B 80                 // 32 ci fp16 (64B) + 16B pad
#define XS_SZ  56160              // 702 rows (26 hh x 27 ww) x 80 B, full plane
#define NXBUF  3
#define BS_SZ  27648              // 18 ks x 32 lane x 48 B
#define NBBUF  2
#define BBASE  (NXBUF*XS_SZ)      // 168480
#define MB_OFF (BBASE + NBBUF*BS_SZ)   // 223776: fX0..2, fB0..1, eX0..2, eB0..1
#define SMEM_BYTES (MB_OFF + 80)  // 223856 (1 CTA/SM)

__device__ __forceinline__ void mma_f16(float* d, const uint32_t* a, uint32_t b0, uint32_t b1) {
    asm volatile(
        "mma.sync.aligned.m16n8k16.row.col.f32.f16.f16.f32 "
        "{%0,%1,%2,%3}, {%4,%5,%6,%7}, {%8,%9}, {%0,%1,%2,%3};"
        : "+f"(d[0]), "+f"(d[1]), "+f"(d[2]), "+f"(d[3])
        : "r"(a[0]), "r"(a[1]), "r"(a[2]), "r"(a[3]), "r"(b0), "r"(b1));
}
__device__ __forceinline__ void ldsm_x4(uint32_t* a, uint32_t addr) {
    asm volatile("ldmatrix.sync.aligned.m8n8.x4.shared.b16 {%0,%1,%2,%3}, [%4];"
                 : "=r"(a[0]), "=r"(a[1]), "=r"(a[2]), "=r"(a[3]) : "r"(addr));
}
__device__ __forceinline__ uint32_t smem_u32(const void* p) {
    uint32_t a;
    asm("{ .reg .u64 t; cvta.to.shared.u64 t, %1; cvt.u32.u64 %0, t; }" : "=r"(a) : "l"(p));
    return a;
}
__device__ __forceinline__ void cpa16(uint32_t dst, const void* src) {
    asm volatile("cp.async.cg.shared.global [%0], [%1], 16;" :: "r"(dst), "l"(src) : "memory");
}
__device__ __forceinline__ void mbar_init(uint32_t mbar, uint32_t cnt) {
    asm volatile("mbarrier.init.shared.b64 [%0], %1;" :: "r"(mbar), "r"(cnt) : "memory");
}
__device__ __forceinline__ void mbar_wait(uint32_t mbar, uint32_t par) {
    asm volatile(
        "{\n\t.reg .pred P;\n\tWL%=:\n\t"
        "mbarrier.try_wait.parity.shared.b64 P, [%0], %1;\n\t"
        "@P bra.uni WD%=;\n\tbra.uni WL%=;\n\tWD%=:\n\t}"
        :: "r"(mbar), "r"(par) : "memory");
}
__device__ __forceinline__ void mbar_arrive(uint32_t mbar) {
    asm volatile("{\n\t.reg .b64 t;\n\tmbarrier.arrive.shared.b64 t, [%0];\n\t}"
                 :: "r"(mbar) : "memory");
}
__device__ __forceinline__ void cpa_arrive_noinc(uint32_t mbar) {
    asm volatile("cp.async.mbarrier.arrive.noinc.shared.b64 [%0];" :: "r"(mbar) : "memory");
}

// ---------------- device globals ----------------
__device__ __half g_xh[4*8*24*24*24*32];         // x as [n][l][d][h][w][ci] fp16
__device__ uint32_t g_w2[9*4608];                // [slab][ks 18][lane 32][8 words]

__global__ void prep_w(const float* __restrict__ w) {
    int o = blockIdx.x * 256 + threadIdx.x;
    if (o >= 9*4608) return;
    int slab = o / 4608;
    int rem  = o % 4608;
    int ks   = rem / 256;
    int lane = (rem % 256) / 8;
    int wd   = rem % 8;
    int nt = wd >> 1, pair = wd & 1;
    int tig = lane & 3, gr = lane >> 2;
    int t = ks >> 1, kc2 = ks & 1;
    int ci = kc2 * 16 + tig * 2 + pair * 8;
    int co = nt * 8 + gr;
    int kh = t / 3, kw = t % 3;
    int kl = slab / 3, kd = slab % 3;
    float w0 = w[(ci * 32 + co) * 81 + kl * 27 + kd * 9 + kh * 3 + kw];
    float w1 = w[((ci + 1) * 32 + co) * 81 + kl * 27 + kd * 9 + kh * 3 + kw];
    __half2 hv = __floats2half2_rn(w0, w1);
    g_w2[o] = *(uint32_t*)&hv;
}

__global__ void __launch_bounds__(576, 2)
prep_x(const float* __restrict__ x) {
    __shared__ uint32_t sx[576*16];
    int plane = blockIdx.x;                  // (n*8+l)*24+d
    int t = threadIdx.x;                     // hw
    int n = plane / 192, l = (plane / 24) % 8, d = plane % 24;
    const float* base = x + (((size_t)(n*32)*8 + l)*24 + d)*576 + t;
#pragma unroll
    for (int ci2 = 0; ci2 < 16; ci2++) {
        float v0 = base[(size_t)(2*ci2)   * 110592];
        float v1 = base[(size_t)(2*ci2+1) * 110592];
        __half2 hv = __floats2half2_rn(v0, v1);
        sx[t*16 + ci2] = *(uint32_t*)&hv;
    }
    __syncthreads();
    uint32_t* gw = (uint32_t*)g_xh + (size_t)plane * 9216;
#pragma unroll
    for (int k = 0; k < 16; k++) gw[k*576 + t] = sx[k*576 + t];
}

__global__ void __launch_bounds__(THREADS, 1)
conv_mma(const float* __restrict__ bias, float* __restrict__ out)
{
    extern __shared__ char smem[];
    const uint32_t sb = smem_u32(smem);

    const int tid  = threadIdx.x;
    const int wid  = tid >> 5;
    const int lane = tid & 31;
    const int gr   = lane >> 2;
    const int tig  = lane & 3;

    const int od = blockIdx.x, ol = blockIdx.y, n = blockIdx.z;
    const int l0 = ol > 0 ? ol - 1 : 0;
    const int l1 = ol < L_ - 1 ? ol + 1 : L_ - 1;
    const int d0 = od > 0 ? od - 1 : 0;
    const int d1 = od < D_ - 1 ? od + 1 : D_ - 1;
    const int nd = d1 - d0 + 1;
    const int ns = (l1 - l0 + 1) * nd;

    const uint32_t mbB = sb + MB_OFF;
    // layout: fX[0..2] @0,8,16 ; fB[0..1] @24,32 ; eX[0..2] @40,48,56 ; eB[0..1] @64,72
    if (tid == 0) {
        mbar_init(mbB + 0, 128);  mbar_init(mbB + 8, 128);  mbar_init(mbB + 16, 128);
        mbar_init(mbB + 24, 128); mbar_init(mbB + 32, 128);
        mbar_init(mbB + 40, 12);  mbar_init(mbB + 48, 12);  mbar_init(mbB + 56, 12);
        mbar_init(mbB + 64, 12);  mbar_init(mbB + 72, 12);
    }

    // ---- halo zero-fill: 126 slots x 3 buffers (rows 0 & 25, side cols ww 0/25/26) ----
    {
        const uint4 z4 = make_uint4(0u, 0u, 0u, 0u);
        for (int i = tid; i < 3 * 126 * 5; i += THREADS) {
            int buf  = i / 630;
            int r    = i % 630;
            int slot = r / 5;
            int seg  = r % 5;
            int q;
            if (slot < 54) {
                q = (slot < 27 ? 0 : 25) * 27 + (slot % 27);
            } else {
                int s2  = slot - 54;          // 0..71
                int row = 1 + s2 / 3;         // 1..24
                int c   = s2 % 3;
                int ww  = (c == 0) ? 0 : 24 + c;   // {0,25,26}
                q = row * 27 + ww;
            }
            *(uint4*)(smem + buf * XS_SZ + q * XROW_B + seg * 16) = z4;
        }
    }
    __syncthreads();   // barriers + halo zero visible; last block-wide sync

    if (wid >= 12) {
        // ========== producer warps (wid 12..15): 128 lanes stage x + B ==========
        const int pl = (wid - 12) * 32 + lane;   // 0..127
        for (int s = 0; s < ns; s++) {
            const int xb_i = s % 3;
            const int bb_i = s & 1;
            if (s >= 3) mbar_wait(mbB + 40 + xb_i * 8, ((s / 3) - 1) & 1);
            if (s >= 2) mbar_wait(mbB + 64 + bb_i * 8, ((s / 2) - 1) & 1);
            const int lp = l0 + s / nd;
            const int dp = d0 + s % nd;
            const int kl = ol + 1 - lp, kd = od + 1 - dp;
            // x: 2304 16B chunks (24 rows x 24 iw x 4)
            const __half* xsrc = g_xh + (size_t)(((n*8 + lp)*24 + dp)) * 576 * 32;
            const uint32_t xb = sb + xb_i * XS_SZ;
            for (int idx = pl; idx < 2304; idx += 128) {
                int ch = idx & 3;
                int r  = idx >> 2;              // 0..575
                int iw = r % 24;
                int hh_l = r / 24 + 1;          // 1..24, ih = hh_l-1
                cpa16(xb + (hh_l * 27 + iw + 1) * XROW_B + ch * 16,
                      xsrc + ((hh_l - 1) * 24 + iw) * 32 + ch * 8);
            }
            cpa_arrive_noinc(mbB + 0 + xb_i * 8);     // fullX
            // B: 1152 16B chunks, gmem 32B groups -> smem 48B stride
            const char* bsrc = (const char*)(g_w2 + (kl * 3 + kd) * 4608);
            const uint32_t bb = sb + BBASE + bb_i * BS_SZ;
            for (int i = pl; i < 1152; i += 128) {
                int grp = i >> 1, half = i & 1;
                cpa16(bb + grp * 48 + half * 16, bsrc + grp * 32 + half * 16);
            }
            cpa_arrive_noinc(mbB + 24 + bb_i * 8);    // fullB
        }
        return;
    }

    // ========== consumer warps (wid 0..11), 3 M-tiles each (M = 576) ==========
    int mb[3];
    uint32_t qa[3];
#pragma unroll
    for (int j = 0; j < 3; j++) {
        mb[j] = (wid * 3 + j) * 16;
        int r = mb[j] + (lane & 7) + ((lane >> 3) & 1) * 8;
        int q = (r / 24) * 27 + (r % 24);
        qa[j] = sb + q * XROW_B + ((lane >> 4) & 1) * 16;
    }
    const int dtap[9] = {56, 55, 54, 29, 28, 27, 2, 1, 0};   // (2-kh)*27+(2-kw)

    float d[48];   // [j 3][nt 4][4]
#pragma unroll
    for (int i = 0; i < 48; i++) d[i] = 0.f;

    for (int s = 0; s < ns; s++) {
        const int xb_i = s % 3;
        const int bb_i = s & 1;
        mbar_wait(mbB + 0 + xb_i * 8, (s / 3) & 1);     // fullX
        mbar_wait(mbB + 24 + bb_i * 8, (s / 2) & 1);    // fullB

        const uint32_t xoff = xb_i * XS_SZ;
        const uint32_t qa0 = qa[0] + xoff, qa1 = qa[1] + xoff, qa2 = qa[2] + xoff;
        const char* bsl = smem + BBASE + bb_i * BS_SZ;

#pragma unroll 9
        for (int t = 0; t < 9; t++) {
            const int dt80 = dtap[t] * XROW_B;
#pragma unroll
            for (int kc2 = 0; kc2 < 2; kc2++) {
                uint32_t a0[4], a1[4], a2[4];
                ldsm_x4(a0, qa0 + dt80 + kc2 * 32);
                ldsm_x4(a1, qa1 + dt80 + kc2 * 32);
                ldsm_x4(a2, qa2 + dt80 + kc2 * 32);
                const uint4* bq = (const uint4*)(bsl + ((t * 2 + kc2) * 32 + lane) * 48);
                uint4 v0 = bq[0], v1 = bq[1];
                mma_f16(d + 0,  a0, v0.x, v0.y);
                mma_f16(d + 16, a1, v0.x, v0.y);
                mma_f16(d + 32, a2, v0.x, v0.y);
                mma_f16(d + 4,  a0, v0.z, v0.w);
                mma_f16(d + 20, a1, v0.z, v0.w);
                mma_f16(d + 36, a2, v0.z, v0.w);
                mma_f16(d + 8,  a0, v1.x, v1.y);
                mma_f16(d + 24, a1, v1.x, v1.y);
                mma_f16(d + 40, a2, v1.x, v1.y);
                mma_f16(d + 12, a0, v1.z, v1.w);
                mma_f16(d + 28, a1, v1.z, v1.w);
                mma_f16(d + 44, a2, v1.z, v1.w);
            }
        }
        if (lane == 0) {
            mbar_arrive(mbB + 40 + xb_i * 8);    // emptyX
            mbar_arrive(mbB + 64 + bb_i * 8);    // emptyB
        }
    }

    // ---- epilogue: bias + store (full plane) ----
    const size_t ob = (((size_t)(n * 32) * 8 + ol) * 24 + od) * 576;
#pragma unroll
    for (int j = 0; j < 3; j++) {
        const int m0 = mb[j] + gr, m1 = m0 + 8;
#pragma unroll
        for (int nt = 0; nt < 4; nt++) {
            const int co0 = nt * 8 + tig * 2;
            const float b0 = __ldg(bias + co0);
            const float b1 = __ldg(bias + co0 + 1);
            const float* dd = d + j * 16 + nt * 4;
            float* o0 = out + ob + (size_t)co0 * 110592;
            float* o1 = o0 + 110592;
            o0[m0] = dd[0] + b0;
            o1[m0] = dd[1] + b1;
            o0[m1] = dd[2] + b0;
            o1[m1] = dd[3] + b1;
        }
    }
}

extern "C" void kernel_launch(void* const* d_in, const int* in_sizes, int n_in,
                              void* d_out, int out_size) {
    const float* x    = (const float*)d_in[0];
    const float* w    = (const float*)d_in[1];
    const float* bias = (const float*)d_in[2];
    float* out = (float*)d_out;

    cudaFuncSetAttribute(conv_mma,
                         cudaFuncAttributeMaxDynamicSharedMemorySize, SMEM_BYTES);

    prep_w<<<162, 256>>>(w);                 // 162*256 == 41472
    prep_x<<<768, 576>>>(x);                 // one block per (n,l,d) plane

    dim3 grid(24, L_, 4);                    // (od, ol, n) — full plane per CTA
    conv_mma<<<grid, THREADS, SMEM_BYTES>>>(bias, out);
}